// round 1
// baseline (speedup 1.0000x reference)
#include <cuda_runtime.h>
#include <cuda_bf16.h>

#define S 128
#define NROWS 4096

// Scratch: 4 arrays of NROWS floats: [bestShift, |scale-1|, sqrt(sum g^2), rowMSE]
__device__ float g_scratch[4 * NROWS];

__global__ void __launch_bounds__(S) loss3_rows(const float* __restrict__ outp,
                                                const float* __restrict__ trut) {
    __shared__ float so2[2 * S];   // output row, duplicated for wrap-free indexing
    __shared__ float st[S];        // truth row
    __shared__ float redv[S];      // argmin value / scratch d-array
    __shared__ float redw[S];      // max / sum reductions
    __shared__ int   redi[S];
    __shared__ float sMse;

    const int row = blockIdx.x;
    const int tid = threadIdx.x;

    const float o = outp[row * S + tid];
    const float t = trut[row * S + tid];
    so2[tid]     = o;
    so2[tid + S] = o;
    st[tid]      = t;
    __syncthreads();

    // ---- shift search: thread tid computes shiftDiff for shift s = tid ----
    // so[(j - tid) & 127] == so2[j + S - tid], with j+S-tid in [1, 255].
    const float* obase = so2 + (S - tid);
    float acc = 0.0f;
#pragma unroll
    for (int j = 0; j < S; j++) {
        float d = obase[j] - st[j];
        acc = fmaf(d, d, acc);
    }
    // thread 0's acc is exactly sum_j (o[j]-t[j])^2 -> row MSE contribution
    if (tid == 0) sMse = acc;

    float sval = sqrtf(acc);  // match reference quantization before argmin

    // ---- argmin (first-index tie-break) + max(output) in one tree ----
    redv[tid] = sval;
    redi[tid] = tid;
    redw[tid] = o;
    __syncthreads();
#pragma unroll
    for (int stp = 64; stp > 0; stp >>= 1) {
        if (tid < stp) {
            float ov = redv[tid + stp];
            int   oi = redi[tid + stp];
            float mv = redv[tid];
            if (ov < mv || (ov == mv && oi < redi[tid])) {
                redv[tid] = ov;
                redi[tid] = oi;
            }
            redw[tid] = fmaxf(redw[tid], redw[tid + stp]);
        }
        __syncthreads();
    }
    const int   b    = redi[0];
    const float maxO = redw[0];
    __syncthreads();

    // ---- max(truth) ----
    redw[tid] = t;
    __syncthreads();
#pragma unroll
    for (int stp = 64; stp > 0; stp >>= 1) {
        if (tid < stp) redw[tid] = fmaxf(redw[tid], redw[tid + stp]);
        __syncthreads();
    }
    const float maxT  = redw[0];
    const float scale = maxT / maxO;

    // ---- detail loss: g = cgrad(scaled - truth) (cgrad is linear) ----
    // rolled[tid] = o[(tid - b) & 127] = so2[tid - b + S]  (index in [1,255])
    const float dval = so2[tid - b + S] * scale - t;
    redv[tid] = dval;
    __syncthreads();   // also orders maxT reads before redw reuse below
    float g = dval - 0.5f * (redv[(tid + S - 1) & (S - 1)] + redv[(tid + 1) & (S - 1)]);
    redw[tid] = g * g;
    __syncthreads();
#pragma unroll
    for (int stp = 64; stp > 0; stp >>= 1) {
        if (tid < stp) redw[tid] += redw[tid + stp];
        __syncthreads();
    }

    if (tid == 0) {
        g_scratch[row]             = (float)b;
        g_scratch[NROWS + row]     = fabsf(scale - 1.0f);
        g_scratch[2 * NROWS + row] = sqrtf(redw[0]);
        g_scratch[3 * NROWS + row] = sMse;
    }
}

__global__ void __launch_bounds__(1024) loss3_final(float* __restrict__ out) {
    __shared__ float4 red[1024];
    const int tid = threadIdx.x;
    float a = 0.0f, b = 0.0f, c = 0.0f, d = 0.0f;
    for (int i = tid; i < NROWS; i += 1024) {
        a += g_scratch[i];
        b += g_scratch[NROWS + i];
        c += g_scratch[2 * NROWS + i];
        d += g_scratch[3 * NROWS + i];
    }
    red[tid] = make_float4(a, b, c, d);
    __syncthreads();
#pragma unroll
    for (int stp = 512; stp > 0; stp >>= 1) {
        if (tid < stp) {
            float4 x = red[tid];
            float4 y = red[tid + stp];
            red[tid] = make_float4(x.x + y.x, x.y + y.y, x.z + y.z, x.w + y.w);
        }
        __syncthreads();
    }
    if (tid == 0) {
        float4 r = red[0];
        out[0] = 50.0f * r.x + 100.0f * r.y + 0.1f * r.z + sqrtf(r.w);
    }
}

extern "C" void kernel_launch(void* const* d_in, const int* in_sizes, int n_in,
                              void* d_out, int out_size) {
    (void)n_in; (void)out_size;
    const float* outp = (const float*)d_in[0];
    const float* trut = (const float*)d_in[1];
    float* res = (float*)d_out;
    const int nrows = in_sizes[0] / S;  // 4096
    loss3_rows<<<nrows, S>>>(outp, trut);
    loss3_final<<<1, 1024>>>(res);
}

// round 2
// speedup vs baseline: 2.3264x; 2.3264x over previous
#include <cuda_runtime.h>
#include <cuda_bf16.h>

#define S 128
#define NROWS 4096
#define RPB 4                 // rows per block (one warp per row)
#define NBLK (NROWS / RPB)    // 1024 blocks

__device__ float4 g_part[NBLK];
__device__ unsigned int g_ticket;   // zero-initialized at load; reset after use

__global__ void __launch_bounds__(128) loss3_fused(const float* __restrict__ outp,
                                                   const float* __restrict__ trut,
                                                   float* __restrict__ out) {
    __shared__ float so2[RPB][2 * S];   // per-row output, duplicated (wrap-free)
    __shared__ float st[RPB][S];        // per-row truth
    __shared__ float4 wres[RPB];
    __shared__ unsigned int sLast;

    const int tid = threadIdx.x;
    const int w = tid >> 5;     // warp = row within block
    const int l = tid & 31;     // lane
    const int row = blockIdx.x * RPB + w;

    // ---- load row (coalesced float4), mirror into smem ----
    float4 o4 = *(const float4*)(outp + row * S + 4 * l);
    float4 t4 = *(const float4*)(trut + row * S + 4 * l);
    *(float4*)&so2[w][4 * l]     = o4;
    *(float4*)&so2[w][S + 4 * l] = o4;
    *(float4*)&st[w][4 * l]      = t4;
    __syncwarp();

    // ---- row MSE (direct), max(output), max(truth): warp shuffles ----
    float d0 = o4.x - t4.x, d1 = o4.y - t4.y, d2 = o4.z - t4.z, d3 = o4.w - t4.w;
    float ms = d0 * d0 + d1 * d1 + d2 * d2 + d3 * d3;
    float mo = fmaxf(fmaxf(o4.x, o4.y), fmaxf(o4.z, o4.w));
    float mt = fmaxf(fmaxf(t4.x, t4.y), fmaxf(t4.z, t4.w));
#pragma unroll
    for (int s = 16; s > 0; s >>= 1) {
        ms += __shfl_xor_sync(0xffffffffu, ms, s);
        mo = fmaxf(mo, __shfl_xor_sync(0xffffffffu, mo, s));
        mt = fmaxf(mt, __shfl_xor_sync(0xffffffffu, mt, s));
    }

    // ---- circular correlation: acc[k] = sum_j o[(j-(4l+k))&127] * t[j] ----
    // o[(j-s)&127] = so2[j - s + S].  base = S - 4l - 4 (16B aligned).
    // window W[m] = so2[base + J + m]; need m = dj + 4 - k, dj,k in 0..3.
    const float* ob = &so2[w][S - 4 * l - 4];
    const float* tb = &st[w][0];
    float acc0 = 0.f, acc1 = 0.f, acc2 = 0.f, acc3 = 0.f;
    float4 W0 = *(const float4*)(ob);            // W[0..3]
#pragma unroll
    for (int J = 0; J < S; J += 4) {
        float4 W1 = *(const float4*)(ob + J + 4);  // W[4..7]
        float4 tt = *(const float4*)(tb + J);      // uniform -> broadcast
        acc0 = fmaf(W1.x, tt.x, acc0);
        acc1 = fmaf(W0.w, tt.x, acc1);
        acc2 = fmaf(W0.z, tt.x, acc2);
        acc3 = fmaf(W0.y, tt.x, acc3);
        acc0 = fmaf(W1.y, tt.y, acc0);
        acc1 = fmaf(W1.x, tt.y, acc1);
        acc2 = fmaf(W0.w, tt.y, acc2);
        acc3 = fmaf(W0.z, tt.y, acc3);
        acc0 = fmaf(W1.z, tt.z, acc0);
        acc1 = fmaf(W1.y, tt.z, acc1);
        acc2 = fmaf(W1.x, tt.z, acc2);
        acc3 = fmaf(W0.w, tt.z, acc3);
        acc0 = fmaf(W1.w, tt.w, acc0);
        acc1 = fmaf(W1.z, tt.w, acc1);
        acc2 = fmaf(W1.y, tt.w, acc2);
        acc3 = fmaf(W1.x, tt.w, acc3);
        W0 = W1;
    }

    // ---- argmax corr == argmin shiftDiff; tie-break -> smaller shift ----
    float bc = acc0; int bs = 4 * l;
    if (acc1 > bc) { bc = acc1; bs = 4 * l + 1; }
    if (acc2 > bc) { bc = acc2; bs = 4 * l + 2; }
    if (acc3 > bc) { bc = acc3; bs = 4 * l + 3; }
#pragma unroll
    for (int s = 16; s > 0; s >>= 1) {
        float oc = __shfl_xor_sync(0xffffffffu, bc, s);
        int   os = __shfl_xor_sync(0xffffffffu, bs, s);
        if (oc > bc || (oc == bc && os < bs)) { bc = oc; bs = os; }
    }
    const int b = bs;
    const float scale = mt / mo;   // max(rolled) == max(output): roll is a permutation

    // ---- detail loss: g = cgrad(rolled*scale - truth), cgrad linear ----
    float gg = 0.f;
#pragma unroll
    for (int m = 0; m < 4; m++) {
        int i = 4 * l + m;
        float dm1 = so2[w][(i - 1 - b) & 127] * scale - st[w][(i - 1) & 127];
        float dc  = so2[w][(i     - b) & 127] * scale - st[w][i];
        float dp1 = so2[w][(i + 1 - b) & 127] * scale - st[w][(i + 1) & 127];
        float g = dc - 0.5f * (dm1 + dp1);
        gg = fmaf(g, g, gg);
    }
#pragma unroll
    for (int s = 16; s > 0; s >>= 1) gg += __shfl_xor_sync(0xffffffffu, gg, s);

    // ---- per-block partial (fixed order: warp 0..3) ----
    if (l == 0) wres[w] = make_float4((float)b, fabsf(scale - 1.0f), sqrtf(gg), ms);
    __syncthreads();
    if (tid == 0) {
        float4 r = wres[0];
#pragma unroll
        for (int k = 1; k < RPB; k++) {
            float4 q = wres[k];
            r.x += q.x; r.y += q.y; r.z += q.z; r.w += q.w;
        }
        g_part[blockIdx.x] = r;
        __threadfence();
        unsigned int old = atomicAdd(&g_ticket, 1u);
        sLast = (old == NBLK - 1) ? 1u : 0u;
    }
    __syncthreads();

    // ---- last block finalizes (deterministic fixed-order reduction) ----
    if (sLast) {
        float a = 0.f, bb = 0.f, c = 0.f, dd = 0.f;
#pragma unroll
        for (int i = tid; i < NBLK; i += 128) {
            float4 q = g_part[i];
            a += q.x; bb += q.y; c += q.z; dd += q.w;
        }
        float4* fr = (float4*)&so2[0][0];   // reuse smem
        fr[tid] = make_float4(a, bb, c, dd);
        __syncthreads();
#pragma unroll
        for (int stp = 64; stp > 0; stp >>= 1) {
            if (tid < stp) {
                float4 x = fr[tid], y = fr[tid + stp];
                fr[tid] = make_float4(x.x + y.x, x.y + y.y, x.z + y.z, x.w + y.w);
            }
            __syncthreads();
        }
        if (tid == 0) {
            float4 r = fr[0];
            out[0] = 50.0f * r.x + 100.0f * r.y + 0.1f * r.z + sqrtf(r.w);
            g_ticket = 0u;   // reset for next graph replay
        }
    }
}

extern "C" void kernel_launch(void* const* d_in, const int* in_sizes, int n_in,
                              void* d_out, int out_size) {
    (void)n_in; (void)out_size; (void)in_sizes;
    const float* outp = (const float*)d_in[0];
    const float* trut = (const float*)d_in[1];
    float* res = (float*)d_out;
    loss3_fused<<<NBLK, 128>>>(outp, trut, res);
}